// round 15
// baseline (speedup 1.0000x reference)
#include <cuda_runtime.h>
#include <cuda_bf16.h>
#include <cuda_fp16.h>
#include <cstdint>

#define BATCH 4
#define SEQ   2048
#define HID   768
#define NHEAD 12
#define HDIM  64
#define NDIM  5
#define MROWS (BATCH*SEQ)   // 8192

#define LOG2E 1.4426950408889634f
#define SOFTC (8.0f * LOG2E)          // fixed softmax offset, log2 domain

// ---------------- scratch (device globals; no allocations allowed) -------------
__device__ float g_y[MROWS*HID];              // pre-LN
__device__ float g_addm[BATCH*SEQ];           // mask -> additive (-C / -1e30), log2 dom

// fp16 operands
__device__ __half g_xf[MROWS*HID];            // input X
__device__ __half g_wf[4*HID*HID];            // weights [q,k,v,o]
__device__ __half g_cf[MROWS*HID];            // ctx (attn out)
// q/k/v fp16, [b,h,s,d]  (q pre-scaled by 0.125*log2e)
__device__ __half g_qf[BATCH*NHEAD*SEQ*HDIM];
__device__ __half g_kf[BATCH*NHEAD*SEQ*HDIM];
__device__ __half g_vf[BATCH*NHEAD*SEQ*HDIM];

// ---------------- HMMA / cp.async / ldmatrix helpers (sm_80+ PTX) --------------
__device__ __forceinline__ uint32_t smem_u32(const void* p) {
    uint32_t a;
    asm("{ .reg .u64 t; cvta.to.shared.u64 t, %1; cvt.u32.u64 %0, t; }" : "=r"(a) : "l"(p));
    return a;
}
__device__ __forceinline__ void cp16(uint32_t s, const void* g) {
    asm volatile("{ .reg .u64 ga; cvta.to.global.u64 ga, %1; "
                 "cp.async.cg.shared.global [%0], [ga], 16; }"
                 :: "r"(s), "l"(g));
}
#define CP_COMMIT() asm volatile("cp.async.commit_group;" ::: "memory")
template<int N> __device__ __forceinline__ void cp_wait() {
    asm volatile("cp.async.wait_group %0;" :: "n"(N) : "memory");
}
__device__ __forceinline__ void mma_f16(float* d, const uint32_t* a, const uint32_t* b) {
    asm volatile(
        "mma.sync.aligned.m16n8k16.row.col.f32.f16.f16.f32 "
        "{%0,%1,%2,%3}, {%4,%5,%6,%7}, {%8,%9}, {%0,%1,%2,%3};"
        : "+f"(d[0]), "+f"(d[1]), "+f"(d[2]), "+f"(d[3])
        : "r"(a[0]), "r"(a[1]), "r"(a[2]), "r"(a[3]), "r"(b[0]), "r"(b[1]));
}
__device__ __forceinline__ void ldsm_x4(uint32_t* r, uint32_t a) {
    asm volatile("ldmatrix.sync.aligned.m8n8.x4.shared.b16 {%0,%1,%2,%3}, [%4];"
                 : "=r"(r[0]), "=r"(r[1]), "=r"(r[2]), "=r"(r[3]) : "r"(a));
}
__device__ __forceinline__ void ldsm_x4t(uint32_t* r, uint32_t a) {
    asm volatile("ldmatrix.sync.aligned.m8n8.x4.trans.shared.b16 {%0,%1,%2,%3}, [%4];"
                 : "=r"(r[0]), "=r"(r[1]), "=r"(r[2]), "=r"(r[3]) : "r"(a));
}
__device__ __forceinline__ uint32_t cvt_h2(float hi, float lo) {
    uint32_t r; asm("cvt.rn.f16x2.f32 %0, %1, %2;" : "=r"(r) : "f"(hi), "f"(lo)); return r;
}
// single-instruction exp2 (MUFU.EX2)
__device__ __forceinline__ float ex2f(float x) {
    float r; asm("ex2.approx.f32 %0, %1;" : "=f"(r) : "f"(x)); return r;
}
// 16B-chunk XOR swizzle: rows 8 apart flip chunk bit 1
__device__ __forceinline__ uint32_t swz(int row, int chunk) {
    return (uint32_t)(chunk ^ (((row >> 3) & 1) << 1));
}

// =====================================================================
// Fused prep: X fp32->fp16, 4 weights fp32->fp16, mask table.
// =====================================================================
#define NX4 (MROWS*HID/4)       // 1572864
#define NW4 (HID*HID/4)         // 147456
#define XBLK (NX4/256)          // 6144
#define WBLK (NW4/256)          // 576

__global__ __launch_bounds__(256) void prep_kernel(
    const float* __restrict__ X,
    const float* __restrict__ W0, const float* __restrict__ W1,
    const float* __restrict__ W2, const float* __restrict__ W3,
    const int* __restrict__ attn_mask)
{
    const int bid = blockIdx.x;
    if (bid < XBLK) {
        int i = bid * 256 + threadIdx.x;
        float4 v = *(const float4*)(X + (size_t)i * 4);
        *(uint2*)(g_xf + (size_t)i * 4) =
            make_uint2(cvt_h2(v.y, v.x), cvt_h2(v.w, v.z));
    } else if (bid < XBLK + 4 * WBLK) {
        int wb = bid - XBLK;
        int which = wb / WBLK;
        int i = (wb - which * WBLK) * 256 + threadIdx.x;
        const float* src = (which == 0) ? W0 : (which == 1) ? W1
                         : (which == 2) ? W2 : W3;
        __half* dst = g_wf + (size_t)which * HID * HID;
        float4 v = *(const float4*)(src + (size_t)i * 4);
        *(uint2*)(dst + (size_t)i * 4) =
            make_uint2(cvt_h2(v.y, v.x), cvt_h2(v.w, v.z));
    } else {
        int i = (bid - XBLK - 4 * WBLK) * 256 + threadIdx.x;
        if (i < BATCH * SEQ)
            g_addm[i] = attn_mask[i] ? -SOFTC : -1.0e30f;
    }
}
#define PREP_BLOCKS (XBLK + 4*WBLK + (BATCH*SEQ + 255)/256)

// =====================================================================
// HMMA GEMM fp16 (R11): BK=64 double-buffered, pitch 72, 128x128 tile.
// QKV (is_oproj=0): writes q/k/v fp16 [b,h,s,d] (q scaled 0.125*log2e).
// O-proj: +bias+residual fp32 -> g_y.
// =====================================================================
#define GP4   72
#define REG4  (128*GP4)
#define BUF4  (2*REG4)
#define GEMM_SMEM_BYTES (2*BUF4*2)   // 73728 B

__global__ __launch_bounds__(256, 2) void hmma_gemm(
    const __half* __restrict__ A,
    const float* __restrict__ b0, const float* __restrict__ b1,
    const float* __restrict__ b2, const float* __restrict__ residual,
    int is_oproj)
{
    extern __shared__ char smraw[];
    const uint32_t sbu = smem_u32(smraw);
    const int tid = threadIdx.x;
    const int lane = tid & 31;
    const int wid = tid >> 5;
    const int wm = wid >> 2;
    const int wn = wid & 3;

    const int n0 = blockIdx.x * 128;
    const int m0 = blockIdx.y * 128;
    const int z  = blockIdx.z;
    const int which = is_oproj ? 3 : z;

    const __half* Bg = g_wf + (size_t)which * HID * HID;
    const float* bias = is_oproj ? b0 : (z == 0 ? b0 : (z == 1 ? b1 : b2));

    float acc[4][4][4];
#pragma unroll
    for (int i = 0; i < 4; i++)
#pragma unroll
        for (int j = 0; j < 4; j++)
#pragma unroll
            for (int r = 0; r < 4; r++) acc[i][j][r] = 0.f;

    auto issue = [&](int c, int buf) {
        const int k0 = c * 64;
        const uint32_t base = sbu + (uint32_t)(buf * BUF4) * 2;
#pragma unroll
        for (int it = 0; it < 4; it++) {
            int idx = tid + it * 256;
            int row = idx >> 3;
            int ch  = idx & 7;
            uint32_t so = (uint32_t)(row * GP4 + swz(row, ch) * 8) * 2;
            cp16(base +          so, A  + (size_t)(m0 + row) * HID + k0 + ch * 8);
            cp16(base + REG4*2 + so, Bg + (size_t)(n0 + row) * HID + k0 + ch * 8);
        }
    };

    issue(0, 0); CP_COMMIT();

    const int NC = HID / 64;   // 12
    for (int c = 0; c < NC; c++) {
        if (c + 1 < NC) { issue(c + 1, (c + 1) & 1); CP_COMMIT(); cp_wait<1>(); }
        else            cp_wait<0>();
        __syncthreads();

        const uint32_t S = sbu + (uint32_t)((c & 1) * BUF4) * 2;

#pragma unroll
        for (int ks = 0; ks < 4; ks++) {
            uint32_t b[2][4];
#pragma unroll
            for (int p = 0; p < 2; p++) {
                int row = wn * 32 + p * 16 + ((lane >> 4) & 1) * 8 + (lane & 7);
                int ch  = ks * 2 + ((lane >> 3) & 1);
                ldsm_x4(b[p], S + REG4 * 2
                              + (uint32_t)(row * GP4 + swz(row, ch) * 8) * 2);
            }
#pragma unroll
            for (int mt = 0; mt < 4; mt++) {
                int row = wm * 64 + mt * 16 + (lane & 15);
                int ch  = ks * 2 + (lane >> 4);
                uint32_t a[4];
                ldsm_x4(a, S + (uint32_t)(row * GP4 + swz(row, ch) * 8) * 2);
#pragma unroll
                for (int p = 0; p < 2; p++) {
                    mma_f16(acc[mt][2*p],   a, b[p]);
                    mma_f16(acc[mt][2*p+1], a, b[p] + 2);
                }
            }
        }
        __syncthreads();
    }

    // ---------------- epilogue ----------------
    const int fr = lane >> 2;
    const int j2 = (lane & 3) * 2;
#pragma unroll
    for (int nt = 0; nt < 4; nt++) {
        const int n = n0 + wn * 32 + nt * 8 + j2;
        const float bv0 = bias[n], bv1 = bias[n + 1];
#pragma unroll
        for (int mt = 0; mt < 4; mt++) {
#pragma unroll
            for (int half = 0; half < 2; half++) {
                const int m = m0 + wm * 64 + mt * 16 + fr + half * 8;
                float v0 = acc[mt][nt][half * 2 + 0];
                float v1 = acc[mt][nt][half * 2 + 1];
                if (!is_oproj) {
                    const float scale = (z == 0) ? (0.125f * LOG2E) : 1.0f;
                    __half* of = (z == 0) ? g_qf : (z == 1 ? g_kf : g_vf);
                    const int bI = m >> 11, sI = m & 2047;
                    const int h = n >> 6, d = n & 63;
                    float s0 = (v0 + bv0) * scale, s1 = (v1 + bv1) * scale;
                    size_t off = ((size_t)(bI * NHEAD + h) * SEQ + sI) * HDIM + d;
                    *(uint32_t*)(of + off) = cvt_h2(s1, s0);
                } else {
                    size_t off = (size_t)m * HID + n;
                    float2 res = *(const float2*)(residual + off);
                    float2 r = make_float2(v0 + bv0 + res.x, v1 + bv1 + res.y);
                    *(float2*)(g_y + off) = r;
                }
            }
        }
    }
}

// =====================================================================
// Flash attention v2: 4 warps x 32 q-rows (halves redundant K/V ldsm).
// 128 threads, 2 CTAs/SM. Fixed-offset softmax per 16-kv chunk.
// =====================================================================
#define AQP 72
#define A_QE    (128*AQP)
#define A_OPE   (128*AQP)
#define A_BUFE  (2*A_OPE)
#define ATTN_SMEM ((A_QE + 2*A_BUFE)*2)   // 92160 B

__global__ __launch_bounds__(128, 2) void attn_hmma(void)
{
    extern __shared__ char smraw[];
    const uint32_t sbu = smem_u32(smraw);

    const int q0 = blockIdx.x * 128;
    const int bh = blockIdx.y;
    const int b  = bh / NHEAD, h = bh % NHEAD;
    const int tid = threadIdx.x;
    const int lane = tid & 31;
    const int w = tid >> 5;           // 0..3, owns q rows [w*32, w*32+32)

    const float* addm = g_addm + b * SEQ;

    const size_t bh_off = (size_t)bh * SEQ * HDIM;
    const __half* qf = g_qf + bh_off + (size_t)q0 * HDIM;

    // Q tile load (group A): 1024 lines / 128 thr
#pragma unroll
    for (int it = 0; it < 8; it++) {
        int idx = tid + it * 128;
        int row = idx >> 3, ch = idx & 7;
        uint32_t so = (uint32_t)(row * AQP + swz(row, ch) * 8) * 2;
        cp16(sbu + so, qf + row * HDIM + ch * 8);
    }
    CP_COMMIT();

    auto issue_kv = [&](int t, int buf) {
        const int kv0 = t * 128;
        uint32_t base = sbu + (uint32_t)(A_QE + buf * A_BUFE) * 2;
        const __half* kf = g_kf + bh_off + (size_t)kv0 * HDIM;
        const __half* vf = g_vf + bh_off + (size_t)kv0 * HDIM;
#pragma unroll
        for (int it = 0; it < 8; it++) {
            int idx = tid + it * 128;
            int row = idx >> 3, ch = idx & 7;
            uint32_t so = (uint32_t)(row * AQP + swz(row, ch) * 8) * 2;
            int go = row * HDIM + ch * 8;
            cp16(base +             so, kf + go);
            cp16(base + A_OPE * 2 + so, vf + go);
        }
    };

    issue_kv(0, 0);
    CP_COMMIT();

    // wait for Q, hoist Q fragments: 2 m-tiles x 4 kt
    cp_wait<1>();
    __syncthreads();
    uint32_t qfr[4][2][4];
#pragma unroll
    for (int kt = 0; kt < 4; kt++)
#pragma unroll
        for (int mt = 0; mt < 2; mt++) {
            int qrow = w * 32 + mt * 16 + (lane & 15);
            int qch  = kt * 2 + (lane >> 4);
            ldsm_x4(qfr[kt][mt],
                    sbu + (uint32_t)(qrow * AQP + swz(qrow, qch) * 8) * 2);
        }

    float O[2][8][4];
    float l[2][2] = {{0.f, 0.f}, {0.f, 0.f}};
#pragma unroll
    for (int mt = 0; mt < 2; mt++)
#pragma unroll
        for (int j = 0; j < 8; j++)
#pragma unroll
            for (int r = 0; r < 4; r++) O[mt][j][r] = 0.f;

    const int ln8 = lane & 7;
    const int sel = lane >> 3;
    const int c2  = (lane & 3) * 2;
    const int fr  = lane >> 2;

    const int NT = SEQ / 128;   // 16
    for (int t = 0; t < NT; t++) {
        if (t + 1 < NT) { issue_kv(t + 1, (t + 1) & 1); CP_COMMIT(); cp_wait<1>(); }
        else            cp_wait<0>();
        __syncthreads();

        const uint32_t kb = sbu + (uint32_t)(A_QE + (t & 1) * A_BUFE) * 2;

#pragma unroll
        for (int sub = 0; sub < 2; sub++) {
            const int r64 = sub * 64;
            const int kv0 = t * 128 + r64;

            // process 16-kv chunks: QK -> softmax -> PV per chunk
#pragma unroll
            for (int jp = 0; jp < 4; jp++) {
                float sacc[2][2][4];
#pragma unroll
                for (int mt = 0; mt < 2; mt++)
#pragma unroll
                    for (int n = 0; n < 2; n++)
#pragma unroll
                        for (int r = 0; r < 4; r++) sacc[mt][n][r] = 0.f;

                // QK^T for 32q x 16kv
#pragma unroll
                for (int kt = 0; kt < 4; kt++) {
                    int krow = r64 + jp * 16 + (sel >> 1) * 8 + ln8;
                    int kch  = kt * 2 + (sel & 1);
                    uint32_t bf[4];
                    ldsm_x4(bf, kb + (uint32_t)(krow * AQP + swz(krow, kch) * 8) * 2);
#pragma unroll
                    for (int mt = 0; mt < 2; mt++) {
                        mma_f16(sacc[mt][0], qfr[kt][mt], bf);
                        mma_f16(sacc[mt][1], qfr[kt][mt], bf + 2);
                    }
                }

                // fixed-offset softmax (log2 domain) on 16 values
                float2 av0 = *(const float2*)&addm[kv0 + jp * 16 + 0 + c2];
                float2 av1 = *(const float2*)&addm[kv0 + jp * 16 + 8 + c2];
                uint32_t pa[2][4];
#pragma unroll
                for (int mt = 0; mt < 2; mt++) {
                    float e00 = ex2f(sacc[mt][0][0] + av0.x);
                    float e01 = ex2f(sacc[mt][0][1] + av0.y);
                    float e02 = ex2f(sacc[mt][0][2] + av0.x);
                    float e03 = ex2f(sacc[mt][0][3] + av0.y);
                    float e10 = ex2f(sacc[mt][1][0] + av1.x);
                    float e11 = ex2f(sacc[mt][1][1] + av1.y);
                    float e12 = ex2f(sacc[mt][1][2] + av1.x);
                    float e13 = ex2f(sacc[mt][1][3] + av1.y);
                    l[mt][0] += e00 + e01 + e10 + e11;   // rows fr
                    l[mt][1] += e02 + e03 + e12 + e13;   // rows fr+8
                    pa[mt][0] = cvt_h2(e01, e00);
                    pa[mt][1] = cvt_h2(e03, e02);
                    pa[mt][2] = cvt_h2(e11, e10);
                    pa[mt][3] = cvt_h2(e13, e12);
                }

                // PV: k-dim = this 16-kv chunk, all 64 d-cols
#pragma unroll
                for (int jd = 0; jd < 4; jd++) {
                    int vrow = r64 + jp * 16 + (sel & 1) * 8 + ln8;
                    int vch  = jd * 2 + (sel >> 1);
                    uint32_t vf[4];
                    ldsm_x4t(vf, kb + A_OPE * 2
                                 + (uint32_t)(vrow * AQP + swz(vrow, vch) * 8) * 2);
#pragma unroll
                    for (int mt = 0; mt < 2; mt++) {
                        mma_f16(O[mt][2*jd],   pa[mt], vf);
                        mma_f16(O[mt][2*jd+1], pa[mt], vf + 2);
                    }
                }
            }
        }
        __syncthreads();
    }

    // ---- epilogue: reduce l across quad lanes, normalize, store fp16 ctx ----
#pragma unroll
    for (int mt = 0; mt < 2; mt++) {
        l[mt][0] += __shfl_xor_sync(0xffffffffu, l[mt][0], 1);
        l[mt][0] += __shfl_xor_sync(0xffffffffu, l[mt][0], 2);
        l[mt][1] += __shfl_xor_sync(0xffffffffu, l[mt][1], 1);
        l[mt][1] += __shfl_xor_sync(0xffffffffu, l[mt][1], 2);
        const float i0 = 1.0f / l[mt][0], i1 = 1.0f / l[mt][1];
        const int q = q0 + w * 32 + mt * 16 + fr;
#pragma unroll
        for (int j = 0; j < 8; j++) {
            const int d = h * HDIM + j * 8 + c2;
            size_t r0 = (size_t)(b * SEQ + q) * HID + d;
            size_t r1 = (size_t)(b * SEQ + q + 8) * HID + d;
            *(uint32_t*)(g_cf + r0) = cvt_h2(O[mt][j][1] * i0, O[mt][j][0] * i0);
            *(uint32_t*)(g_cf + r1) = cvt_h2(O[mt][j][3] * i1, O[mt][j][2] * i1);
        }
    }
}

// =====================================================================
// LayerNorm over last dim (768): 192 threads x float4 per row
// =====================================================================
__global__ __launch_bounds__(192) void ln_kernel(
    const float* __restrict__ gamma, const float* __restrict__ beta,
    float* __restrict__ out)
{
    const int r = blockIdx.x;
    const float* row = g_y + (size_t)r * HID;
    const int tid = threadIdx.x;

    float4 v = *(const float4*)(row + tid * 4);
    float s  = v.x + v.y + v.z + v.w;
    float s2 = v.x*v.x + v.y*v.y + v.z*v.z + v.w*v.w;
#pragma unroll
    for (int off = 16; off; off >>= 1) {
        s  += __shfl_xor_sync(0xffffffffu, s,  off);
        s2 += __shfl_xor_sync(0xffffffffu, s2, off);
    }
    __shared__ float sm_s[6], sm_s2[6];
    int w = tid >> 5, lane = tid & 31;
    if (lane == 0) { sm_s[w] = s; sm_s2[w] = s2; }
    __syncthreads();
    if (tid == 0) {
        float a = 0.f, b2 = 0.f;
#pragma unroll
        for (int i = 0; i < 6; i++) { a += sm_s[i]; b2 += sm_s2[i]; }
        sm_s[0] = a; sm_s2[0] = b2;
    }
    __syncthreads();
    s = sm_s[0]; s2 = sm_s2[0];

    float mean = s * (1.0f / HID);
    float var  = s2 * (1.0f / HID) - mean * mean;
    float rstd = rsqrtf(var + 1e-5f);

    float4 g = *(const float4*)(gamma + tid * 4);
    float4 bb = *(const float4*)(beta + tid * 4);
    float4 o;
    o.x = (v.x - mean) * rstd * g.x + bb.x;
    o.y = (v.y - mean) * rstd * g.y + bb.y;
    o.z = (v.z - mean) * rstd * g.z + bb.z;
    o.w = (v.w - mean) * rstd * g.w + bb.w;
    *(float4*)(out + (size_t)r * HID + tid * 4) = o;
}

// =====================================================================
extern "C" void kernel_launch(void* const* d_in, const int* in_sizes, int n_in,
                              void* d_out, int out_size)
{
    const float* hidden     = (const float*)d_in[0];
    const float* Wq         = (const float*)d_in[1];
    const float* bq         = (const float*)d_in[2];
    const float* Wk         = (const float*)d_in[3];
    const float* bk         = (const float*)d_in[4];
    const float* Wv         = (const float*)d_in[5];
    const float* bv         = (const float*)d_in[6];
    const float* Wo         = (const float*)d_in[7];
    const float* bo         = (const float*)d_in[8];
    const float* ln_gamma   = (const float*)d_in[10];
    const float* ln_beta    = (const float*)d_in[11];
    const int*   attn_mask  = (const int*)d_in[12];
    float* out = (float*)d_out;

    cudaFuncSetAttribute(hmma_gemm, cudaFuncAttributeMaxDynamicSharedMemorySize,
                         GEMM_SMEM_BYTES);
    cudaFuncSetAttribute(attn_hmma, cudaFuncAttributeMaxDynamicSharedMemorySize,
                         ATTN_SMEM);

    __half *xf, *cf;
    cudaGetSymbolAddress((void**)&xf, g_xf);
    cudaGetSymbolAddress((void**)&cf, g_cf);

    // fused prep: converts + mask table
    prep_kernel<<<PREP_BLOCKS, 256>>>(hidden, Wq, Wk, Wv, Wo, attn_mask);

    // QKV projections -> fp16 q/k/v (q in log2-softmax scale)
    hmma_gemm<<<dim3(HID/128, MROWS/128, 3), 256, GEMM_SMEM_BYTES>>>(
        xf, bq, bk, bv, nullptr, 0);

    // attention (fixed-offset softmax, 4-warp CTA) -> ctx fp16
    attn_hmma<<<dim3(SEQ/128, BATCH*NHEAD), 128, ATTN_SMEM>>>();

    // O projection (+bias +residual) -> g_y
    hmma_gemm<<<dim3(HID/128, MROWS/128, 1), 256, GEMM_SMEM_BYTES>>>(
        cf, bo, nullptr, nullptr, hidden, 1);

    // layernorm
    ln_kernel<<<MROWS, 192>>>(ln_gamma, ln_beta, out);
}

// round 16
// speedup vs baseline: 1.0392x; 1.0392x over previous
#include <cuda_runtime.h>
#include <cuda_bf16.h>
#include <cuda_fp16.h>
#include <cstdint>

#define BATCH 4
#define SEQ   2048
#define HID   768
#define NHEAD 12
#define HDIM  64
#define NDIM  5
#define MROWS (BATCH*SEQ)   // 8192

#define LOG2E 1.4426950408889634f
#define SOFTC (8.0f * LOG2E)          // fixed softmax offset, log2 domain

// ---------------- scratch (device globals; no allocations allowed) -------------
__device__ float g_y[MROWS*HID];              // pre-LN
__device__ float g_addm[BATCH*SEQ];           // mask -> additive (-C / -1e30), log2 dom

// fp16 operands
__device__ __half g_xf[MROWS*HID];            // input X
__device__ __half g_wf[4*HID*HID];            // weights [q,k,v,o]
__device__ __half g_cf[MROWS*HID];            // ctx (attn out)
// q/k/v fp16, [b,h,s,d]  (q pre-scaled by 0.125*log2e)
__device__ __half g_qf[BATCH*NHEAD*SEQ*HDIM];
__device__ __half g_kf[BATCH*NHEAD*SEQ*HDIM];
__device__ __half g_vf[BATCH*NHEAD*SEQ*HDIM];

// ---------------- HMMA / cp.async / ldmatrix helpers (sm_80+ PTX) --------------
__device__ __forceinline__ uint32_t smem_u32(const void* p) {
    uint32_t a;
    asm("{ .reg .u64 t; cvta.to.shared.u64 t, %1; cvt.u32.u64 %0, t; }" : "=r"(a) : "l"(p));
    return a;
}
__device__ __forceinline__ void cp16(uint32_t s, const void* g) {
    asm volatile("{ .reg .u64 ga; cvta.to.global.u64 ga, %1; "
                 "cp.async.cg.shared.global [%0], [ga], 16; }"
                 :: "r"(s), "l"(g));
}
#define CP_COMMIT() asm volatile("cp.async.commit_group;" ::: "memory")
template<int N> __device__ __forceinline__ void cp_wait() {
    asm volatile("cp.async.wait_group %0;" :: "n"(N) : "memory");
}
__device__ __forceinline__ void mma_f16(float* d, const uint32_t* a, const uint32_t* b) {
    asm volatile(
        "mma.sync.aligned.m16n8k16.row.col.f32.f16.f16.f32 "
        "{%0,%1,%2,%3}, {%4,%5,%6,%7}, {%8,%9}, {%0,%1,%2,%3};"
        : "+f"(d[0]), "+f"(d[1]), "+f"(d[2]), "+f"(d[3])
        : "r"(a[0]), "r"(a[1]), "r"(a[2]), "r"(a[3]), "r"(b[0]), "r"(b[1]));
}
__device__ __forceinline__ void ldsm_x4(uint32_t* r, uint32_t a) {
    asm volatile("ldmatrix.sync.aligned.m8n8.x4.shared.b16 {%0,%1,%2,%3}, [%4];"
                 : "=r"(r[0]), "=r"(r[1]), "=r"(r[2]), "=r"(r[3]) : "r"(a));
}
__device__ __forceinline__ void ldsm_x4t(uint32_t* r, uint32_t a) {
    asm volatile("ldmatrix.sync.aligned.m8n8.x4.trans.shared.b16 {%0,%1,%2,%3}, [%4];"
                 : "=r"(r[0]), "=r"(r[1]), "=r"(r[2]), "=r"(r[3]) : "r"(a));
}
__device__ __forceinline__ uint32_t cvt_h2(float hi, float lo) {
    uint32_t r; asm("cvt.rn.f16x2.f32 %0, %1, %2;" : "=r"(r) : "f"(hi), "f"(lo)); return r;
}
// single-instruction exp2 (MUFU.EX2)
__device__ __forceinline__ float ex2f(float x) {
    float r; asm("ex2.approx.f32 %0, %1;" : "=f"(r) : "f"(x)); return r;
}
// 16B-chunk XOR swizzle: rows 8 apart flip chunk bit 1
__device__ __forceinline__ uint32_t swz(int row, int chunk) {
    return (uint32_t)(chunk ^ (((row >> 3) & 1) << 1));
}

// =====================================================================
// Fused prep: X fp32->fp16, 4 weights fp32->fp16, mask table.
// =====================================================================
#define NX4 (MROWS*HID/4)       // 1572864
#define NW4 (HID*HID/4)         // 147456
#define XBLK (NX4/256)          // 6144
#define WBLK (NW4/256)          // 576

__global__ __launch_bounds__(256) void prep_kernel(
    const float* __restrict__ X,
    const float* __restrict__ W0, const float* __restrict__ W1,
    const float* __restrict__ W2, const float* __restrict__ W3,
    const int* __restrict__ attn_mask)
{
    const int bid = blockIdx.x;
    if (bid < XBLK) {
        int i = bid * 256 + threadIdx.x;
        float4 v = *(const float4*)(X + (size_t)i * 4);
        *(uint2*)(g_xf + (size_t)i * 4) =
            make_uint2(cvt_h2(v.y, v.x), cvt_h2(v.w, v.z));
    } else if (bid < XBLK + 4 * WBLK) {
        int wb = bid - XBLK;
        int which = wb / WBLK;
        int i = (wb - which * WBLK) * 256 + threadIdx.x;
        const float* src = (which == 0) ? W0 : (which == 1) ? W1
                         : (which == 2) ? W2 : W3;
        __half* dst = g_wf + (size_t)which * HID * HID;
        float4 v = *(const float4*)(src + (size_t)i * 4);
        *(uint2*)(dst + (size_t)i * 4) =
            make_uint2(cvt_h2(v.y, v.x), cvt_h2(v.w, v.z));
    } else {
        int i = (bid - XBLK - 4 * WBLK) * 256 + threadIdx.x;
        if (i < BATCH * SEQ)
            g_addm[i] = attn_mask[i] ? -SOFTC : -1.0e30f;
    }
}
#define PREP_BLOCKS (XBLK + 4*WBLK + (BATCH*SEQ + 255)/256)

// =====================================================================
// HMMA GEMM fp16 (R11): BK=64 double-buffered, pitch 72, 128x128 tile.
// QKV (is_oproj=0): writes q/k/v fp16 [b,h,s,d] (q scaled 0.125*log2e).
// O-proj: +bias+residual fp32 -> g_y.
// =====================================================================
#define GP4   72
#define REG4  (128*GP4)
#define BUF4  (2*REG4)
#define GEMM_SMEM_BYTES (2*BUF4*2)   // 73728 B

__global__ __launch_bounds__(256, 2) void hmma_gemm(
    const __half* __restrict__ A,
    const float* __restrict__ b0, const float* __restrict__ b1,
    const float* __restrict__ b2, const float* __restrict__ residual,
    int is_oproj)
{
    extern __shared__ char smraw[];
    const uint32_t sbu = smem_u32(smraw);
    const int tid = threadIdx.x;
    const int lane = tid & 31;
    const int wid = tid >> 5;
    const int wm = wid >> 2;
    const int wn = wid & 3;

    const int n0 = blockIdx.x * 128;
    const int m0 = blockIdx.y * 128;
    const int z  = blockIdx.z;
    const int which = is_oproj ? 3 : z;

    const __half* Bg = g_wf + (size_t)which * HID * HID;
    const float* bias = is_oproj ? b0 : (z == 0 ? b0 : (z == 1 ? b1 : b2));

    float acc[4][4][4];
#pragma unroll
    for (int i = 0; i < 4; i++)
#pragma unroll
        for (int j = 0; j < 4; j++)
#pragma unroll
            for (int r = 0; r < 4; r++) acc[i][j][r] = 0.f;

    auto issue = [&](int c, int buf) {
        const int k0 = c * 64;
        const uint32_t base = sbu + (uint32_t)(buf * BUF4) * 2;
#pragma unroll
        for (int it = 0; it < 4; it++) {
            int idx = tid + it * 256;
            int row = idx >> 3;
            int ch  = idx & 7;
            uint32_t so = (uint32_t)(row * GP4 + swz(row, ch) * 8) * 2;
            cp16(base +          so, A  + (size_t)(m0 + row) * HID + k0 + ch * 8);
            cp16(base + REG4*2 + so, Bg + (size_t)(n0 + row) * HID + k0 + ch * 8);
        }
    };

    issue(0, 0); CP_COMMIT();

    const int NC = HID / 64;   // 12
    for (int c = 0; c < NC; c++) {
        if (c + 1 < NC) { issue(c + 1, (c + 1) & 1); CP_COMMIT(); cp_wait<1>(); }
        else            cp_wait<0>();
        __syncthreads();

        const uint32_t S = sbu + (uint32_t)((c & 1) * BUF4) * 2;

#pragma unroll
        for (int ks = 0; ks < 4; ks++) {
            uint32_t b[2][4];
#pragma unroll
            for (int p = 0; p < 2; p++) {
                int row = wn * 32 + p * 16 + ((lane >> 4) & 1) * 8 + (lane & 7);
                int ch  = ks * 2 + ((lane >> 3) & 1);
                ldsm_x4(b[p], S + REG4 * 2
                              + (uint32_t)(row * GP4 + swz(row, ch) * 8) * 2);
            }
#pragma unroll
            for (int mt = 0; mt < 4; mt++) {
                int row = wm * 64 + mt * 16 + (lane & 15);
                int ch  = ks * 2 + (lane >> 4);
                uint32_t a[4];
                ldsm_x4(a, S + (uint32_t)(row * GP4 + swz(row, ch) * 8) * 2);
#pragma unroll
                for (int p = 0; p < 2; p++) {
                    mma_f16(acc[mt][2*p],   a, b[p]);
                    mma_f16(acc[mt][2*p+1], a, b[p] + 2);
                }
            }
        }
        __syncthreads();
    }

    // ---------------- epilogue ----------------
    const int fr = lane >> 2;
    const int j2 = (lane & 3) * 2;
#pragma unroll
    for (int nt = 0; nt < 4; nt++) {
        const int n = n0 + wn * 32 + nt * 8 + j2;
        const float bv0 = bias[n], bv1 = bias[n + 1];
#pragma unroll
        for (int mt = 0; mt < 4; mt++) {
#pragma unroll
            for (int half = 0; half < 2; half++) {
                const int m = m0 + wm * 64 + mt * 16 + fr + half * 8;
                float v0 = acc[mt][nt][half * 2 + 0];
                float v1 = acc[mt][nt][half * 2 + 1];
                if (!is_oproj) {
                    const float scale = (z == 0) ? (0.125f * LOG2E) : 1.0f;
                    __half* of = (z == 0) ? g_qf : (z == 1 ? g_kf : g_vf);
                    const int bI = m >> 11, sI = m & 2047;
                    const int h = n >> 6, d = n & 63;
                    float s0 = (v0 + bv0) * scale, s1 = (v1 + bv1) * scale;
                    size_t off = ((size_t)(bI * NHEAD + h) * SEQ + sI) * HDIM + d;
                    *(uint32_t*)(of + off) = cvt_h2(s1, s0);
                } else {
                    size_t off = (size_t)m * HID + n;
                    float2 res = *(const float2*)(residual + off);
                    float2 r = make_float2(v0 + bv0 + res.x, v1 + bv1 + res.y);
                    *(float2*)(g_y + off) = r;
                }
            }
        }
    }
}

// =====================================================================
// Flash attention (R11 champion): fp16 HMMA, fixed-offset softmax,
// Q frags hoisted to registers, KV staged 128/buffer, 8 warps.
// =====================================================================
#define AQP 72
#define A_QE    (128*AQP)
#define A_OPE   (128*AQP)
#define A_BUFE  (2*A_OPE)
#define ATTN_SMEM ((A_QE + 2*A_BUFE)*2)   // 92160 B

__global__ __launch_bounds__(256, 2) void attn_hmma(void)
{
    extern __shared__ char smraw[];
    const uint32_t sbu = smem_u32(smraw);

    const int q0 = blockIdx.x * 128;
    const int bh = blockIdx.y;
    const int b  = bh / NHEAD, h = bh % NHEAD;
    const int tid = threadIdx.x;
    const int lane = tid & 31;
    const int w = tid >> 5;

    const float* addm = g_addm + b * SEQ;

    const size_t bh_off = (size_t)bh * SEQ * HDIM;
    const __half* qf = g_qf + bh_off + (size_t)q0 * HDIM;

    // Q tile load (group A)
#pragma unroll
    for (int it = 0; it < 4; it++) {
        int idx = tid + it * 256;
        int row = idx >> 3, ch = idx & 7;
        uint32_t so = (uint32_t)(row * AQP + swz(row, ch) * 8) * 2;
        cp16(sbu + so, qf + row * HDIM + ch * 8);
    }
    CP_COMMIT();

    auto issue_kv = [&](int t, int buf) {
        const int kv0 = t * 128;
        uint32_t base = sbu + (uint32_t)(A_QE + buf * A_BUFE) * 2;
        const __half* kf = g_kf + bh_off + (size_t)kv0 * HDIM;
        const __half* vf = g_vf + bh_off + (size_t)kv0 * HDIM;
#pragma unroll
        for (int it = 0; it < 4; it++) {
            int idx = tid + it * 256;
            int row = idx >> 3, ch = idx & 7;
            uint32_t so = (uint32_t)(row * AQP + swz(row, ch) * 8) * 2;
            int go = row * HDIM + ch * 8;
            cp16(base +             so, kf + go);
            cp16(base + A_OPE * 2 + so, vf + go);
        }
    };

    issue_kv(0, 0);
    CP_COMMIT();

    // wait for Q, hoist Q fragments
    cp_wait<1>();
    __syncthreads();
    uint32_t qfr[4][4];
#pragma unroll
    for (int kt = 0; kt < 4; kt++) {
        int qrow = w * 16 + (lane & 15);
        int qch  = kt * 2 + (lane >> 4);
        ldsm_x4(qfr[kt], sbu + (uint32_t)(qrow * AQP + swz(qrow, qch) * 8) * 2);
    }

    float S[8][4], O[8][4];
    float l0 = 0.f, l1 = 0.f;
#pragma unroll
    for (int j = 0; j < 8; j++)
#pragma unroll
        for (int r = 0; r < 4; r++) O[j][r] = 0.f;

    const int ln8 = lane & 7;
    const int sel = lane >> 3;
    const int c2  = (lane & 3) * 2;
    const int fr  = lane >> 2;

    const int NT = SEQ / 128;   // 16
    for (int t = 0; t < NT; t++) {
        if (t + 1 < NT) { issue_kv(t + 1, (t + 1) & 1); CP_COMMIT(); cp_wait<1>(); }
        else            cp_wait<0>();
        __syncthreads();

        const uint32_t kb = sbu + (uint32_t)(A_QE + (t & 1) * A_BUFE) * 2;

#pragma unroll
        for (int sub = 0; sub < 2; sub++) {
            const int r64 = sub * 64;

#pragma unroll
            for (int j = 0; j < 8; j++)
#pragma unroll
                for (int r = 0; r < 4; r++) S[j][r] = 0.f;

            // ---- QK^T (Q frags from registers) ----
#pragma unroll
            for (int kt = 0; kt < 4; kt++) {
#pragma unroll
                for (int jp = 0; jp < 4; jp++) {
                    int krow = r64 + jp * 16 + (sel >> 1) * 8 + ln8;
                    int kch  = kt * 2 + (sel & 1);
                    uint32_t boff = (uint32_t)(krow * AQP + swz(krow, kch) * 8) * 2;
                    uint32_t bf[4];
                    ldsm_x4(bf, kb + boff);
                    mma_f16(S[2*jp],   qfr[kt], bf);
                    mma_f16(S[2*jp+1], qfr[kt], bf + 2);
                }
            }

            // ---- fixed-offset softmax: p = ex2(s' + addm) ----
            const int kv0 = t * 128 + r64;
#pragma unroll
            for (int j = 0; j < 8; j++) {
                float2 av = *(const float2*)&addm[kv0 + j * 8 + c2];
                S[j][0] = ex2f(S[j][0] + av.x);
                S[j][1] = ex2f(S[j][1] + av.y);
                S[j][2] = ex2f(S[j][2] + av.x);
                S[j][3] = ex2f(S[j][3] + av.y);
                l0 += S[j][0] + S[j][1];
                l1 += S[j][2] + S[j][3];
            }

            // ---- P pack fp16 and PV ----
#pragma unroll
            for (int kt2 = 0; kt2 < 4; kt2++) {
                uint32_t pa[4];
#pragma unroll
                for (int half = 0; half < 2; half++) {
                    const int jt = 2 * kt2 + half;
                    pa[half * 2 + 0] = cvt_h2(S[jt][1], S[jt][0]);
                    pa[half * 2 + 1] = cvt_h2(S[jt][3], S[jt][2]);
                }
#pragma unroll
                for (int jp = 0; jp < 4; jp++) {
                    int vrow = r64 + kt2 * 16 + (sel & 1) * 8 + ln8;
                    int vch  = jp * 2 + (sel >> 1);
                    uint32_t voff = (uint32_t)(vrow * AQP + swz(vrow, vch) * 8) * 2;
                    uint32_t vf[4];
                    ldsm_x4t(vf, kb + A_OPE * 2 + voff);
                    mma_f16(O[2*jp],   pa, vf);
                    mma_f16(O[2*jp+1], pa, vf + 2);
                }
            }
        }
        __syncthreads();
    }

    // ---- epilogue: one cross-lane reduction, normalize, store fp16 ctx ----
    l0 += __shfl_xor_sync(0xffffffffu, l0, 1);
    l0 += __shfl_xor_sync(0xffffffffu, l0, 2);
    l1 += __shfl_xor_sync(0xffffffffu, l1, 1);
    l1 += __shfl_xor_sync(0xffffffffu, l1, 2);
    const float i0 = 1.0f / l0, i1 = 1.0f / l1;
    const int q = q0 + w * 16 + fr;
#pragma unroll
    for (int j = 0; j < 8; j++) {
        const int d = h * HDIM + j * 8 + c2;
        size_t r0 = (size_t)(b * SEQ + q) * HID + d;
        size_t r1 = (size_t)(b * SEQ + q + 8) * HID + d;
        *(uint32_t*)(g_cf + r0) = cvt_h2(O[j][1] * i0, O[j][0] * i0);
        *(uint32_t*)(g_cf + r1) = cvt_h2(O[j][3] * i1, O[j][2] * i1);
    }
}

// =====================================================================
// LayerNorm over last dim (768): 192 threads x float4 per row
// =====================================================================
__global__ __launch_bounds__(192) void ln_kernel(
    const float* __restrict__ gamma, const float* __restrict__ beta,
    float* __restrict__ out)
{
    const int r = blockIdx.x;
    const float* row = g_y + (size_t)r * HID;
    const int tid = threadIdx.x;

    float4 v = *(const float4*)(row + tid * 4);
    float s  = v.x + v.y + v.z + v.w;
    float s2 = v.x*v.x + v.y*v.y + v.z*v.z + v.w*v.w;
#pragma unroll
    for (int off = 16; off; off >>= 1) {
        s  += __shfl_xor_sync(0xffffffffu, s,  off);
        s2 += __shfl_xor_sync(0xffffffffu, s2, off);
    }
    __shared__ float sm_s[6], sm_s2[6];
    int w = tid >> 5, lane = tid & 31;
    if (lane == 0) { sm_s[w] = s; sm_s2[w] = s2; }
    __syncthreads();
    if (tid == 0) {
        float a = 0.f, b2 = 0.f;
#pragma unroll
        for (int i = 0; i < 6; i++) { a += sm_s[i]; b2 += sm_s2[i]; }
        sm_s[0] = a; sm_s2[0] = b2;
    }
    __syncthreads();
    s = sm_s[0]; s2 = sm_s2[0];

    float mean = s * (1.0f / HID);
    float var  = s2 * (1.0f / HID) - mean * mean;
    float rstd = rsqrtf(var + 1e-5f);

    float4 g = *(const float4*)(gamma + tid * 4);
    float4 bb = *(const float4*)(beta + tid * 4);
    float4 o;
    o.x = (v.x - mean) * rstd * g.x + bb.x;
    o.y = (v.y - mean) * rstd * g.y + bb.y;
    o.z = (v.z - mean) * rstd * g.z + bb.z;
    o.w = (v.w - mean) * rstd * g.w + bb.w;
    *(float4*)(out + (size_t)r * HID + tid * 4) = o;
}

// =====================================================================
extern "C" void kernel_launch(void* const* d_in, const int* in_sizes, int n_in,
                              void* d_out, int out_size)
{
    const float* hidden     = (const float*)d_in[0];
    const float* Wq         = (const float*)d_in[1];
    const float* bq         = (const float*)d_in[2];
    const float* Wk         = (const float*)d_in[3];
    const float* bk         = (const float*)d_in[4];
    const float* Wv         = (const float*)d_in[5];
    const float* bv         = (const float*)d_in[6];
    const float* Wo         = (const float*)d_in[7];
    const float* bo         = (const float*)d_in[8];
    const float* ln_gamma   = (const float*)d_in[10];
    const float* ln_beta    = (const float*)d_in[11];
    const int*   attn_mask  = (const int*)d_in[12];
    float* out = (float*)d_out;

    cudaFuncSetAttribute(hmma_gemm, cudaFuncAttributeMaxDynamicSharedMemorySize,
                         GEMM_SMEM_BYTES);
    cudaFuncSetAttribute(attn_hmma, cudaFuncAttributeMaxDynamicSharedMemorySize,
                         ATTN_SMEM);

    __half *xf, *cf;
    cudaGetSymbolAddress((void**)&xf, g_xf);
    cudaGetSymbolAddress((void**)&cf, g_cf);

    // fused prep: converts + mask table
    prep_kernel<<<PREP_BLOCKS, 256>>>(hidden, Wq, Wk, Wv, Wo, attn_mask);

    // QKV projections -> fp16 q/k/v (q in log2-softmax scale)
    hmma_gemm<<<dim3(HID/128, MROWS/128, 3), 256, GEMM_SMEM_BYTES>>>(
        xf, bq, bk, bv, nullptr, 0);

    // attention (fixed-offset softmax) -> ctx fp16
    attn_hmma<<<dim3(SEQ/128, BATCH*NHEAD), 256, ATTN_SMEM>>>();

    // O projection (+bias +residual) -> g_y
    hmma_gemm<<<dim3(HID/128, MROWS/128, 1), 256, GEMM_SMEM_BYTES>>>(
        cf, bo, nullptr, nullptr, hidden, 1);

    // layernorm
    ln_kernel<<<MROWS, 192>>>(ln_gamma, ln_beta, out);
}

// round 17
// speedup vs baseline: 1.3387x; 1.2882x over previous
#include <cuda_runtime.h>
#include <cuda_bf16.h>
#include <cuda_fp16.h>
#include <cstdint>

#define BATCH 4
#define SEQ   2048
#define HID   768
#define NHEAD 12
#define HDIM  64
#define NDIM  5
#define MROWS (BATCH*SEQ)   // 8192

#define LOG2E 1.4426950408889634f
#define SOFTC (8.0f * LOG2E)          // fixed softmax offset, log2 domain

// ---------------- scratch (device globals; no allocations allowed) -------------
__device__ float g_y[MROWS*HID];              // pre-LN
__device__ float g_addm[BATCH*SEQ];           // compact additive (-C / -1e30 pad)
__device__ int   g_cidx[BATCH*SEQ];           // orig pos -> compact pos (-1 masked)
__device__ int   g_valid[BATCH];              // valid key count per batch

// fp16 operands
__device__ __half g_xf[MROWS*HID];            // input X
__device__ __half g_wf[4*HID*HID];            // weights [q,k,v,o]
__device__ __half g_cf[MROWS*HID];            // ctx (attn out)
// q uncompacted; k/v COMPACTED along seq, [b,h,j,d]
__device__ __half g_qf[BATCH*NHEAD*SEQ*HDIM];
__device__ __half g_kf[BATCH*NHEAD*SEQ*HDIM];
__device__ __half g_vf[BATCH*NHEAD*SEQ*HDIM];

// ---------------- HMMA / cp.async / ldmatrix helpers (sm_80+ PTX) --------------
__device__ __forceinline__ uint32_t smem_u32(const void* p) {
    uint32_t a;
    asm("{ .reg .u64 t; cvta.to.shared.u64 t, %1; cvt.u32.u64 %0, t; }" : "=r"(a) : "l"(p));
    return a;
}
__device__ __forceinline__ void cp16(uint32_t s, const void* g) {
    asm volatile("{ .reg .u64 ga; cvta.to.global.u64 ga, %1; "
                 "cp.async.cg.shared.global [%0], [ga], 16; }"
                 :: "r"(s), "l"(g));
}
#define CP_COMMIT() asm volatile("cp.async.commit_group;" ::: "memory")
template<int N> __device__ __forceinline__ void cp_wait() {
    asm volatile("cp.async.wait_group %0;" :: "n"(N) : "memory");
}
__device__ __forceinline__ void mma_f16(float* d, const uint32_t* a, const uint32_t* b) {
    asm volatile(
        "mma.sync.aligned.m16n8k16.row.col.f32.f16.f16.f32 "
        "{%0,%1,%2,%3}, {%4,%5,%6,%7}, {%8,%9}, {%0,%1,%2,%3};"
        : "+f"(d[0]), "+f"(d[1]), "+f"(d[2]), "+f"(d[3])
        : "r"(a[0]), "r"(a[1]), "r"(a[2]), "r"(a[3]), "r"(b[0]), "r"(b[1]));
}
__device__ __forceinline__ void ldsm_x4(uint32_t* r, uint32_t a) {
    asm volatile("ldmatrix.sync.aligned.m8n8.x4.shared.b16 {%0,%1,%2,%3}, [%4];"
                 : "=r"(r[0]), "=r"(r[1]), "=r"(r[2]), "=r"(r[3]) : "r"(a));
}
__device__ __forceinline__ void ldsm_x4t(uint32_t* r, uint32_t a) {
    asm volatile("ldmatrix.sync.aligned.m8n8.x4.trans.shared.b16 {%0,%1,%2,%3}, [%4];"
                 : "=r"(r[0]), "=r"(r[1]), "=r"(r[2]), "=r"(r[3]) : "r"(a));
}
__device__ __forceinline__ uint32_t cvt_h2(float hi, float lo) {
    uint32_t r; asm("cvt.rn.f16x2.f32 %0, %1, %2;" : "=r"(r) : "f"(hi), "f"(lo)); return r;
}
// single-instruction exp2 (MUFU.EX2)
__device__ __forceinline__ float ex2f(float x) {
    float r; asm("ex2.approx.f32 %0, %1;" : "=f"(r) : "f"(x)); return r;
}
// 16B-chunk XOR swizzle: rows 8 apart flip chunk bit 1
__device__ __forceinline__ uint32_t swz(int row, int chunk) {
    return (uint32_t)(chunk ^ (((row >> 3) & 1) << 1));
}

// =====================================================================
// Mask scan: per batch, compact index map + valid count + additive table.
// Masked keys contribute exactly 0 to softmax num & denom -> removable.
// =====================================================================
__global__ __launch_bounds__(256) void scan_kernel(const int* __restrict__ attn_mask)
{
    __shared__ int tsum[256];
    __shared__ int total_sh;
    const int b = blockIdx.x;
    const int tid = threadIdx.x;
    const int* m = attn_mask + b * SEQ;
    const int base = tid * 8;
    int v[8]; int cnt = 0;
#pragma unroll
    for (int i = 0; i < 8; i++) { v[i] = (m[base + i] != 0) ? 1 : 0; cnt += v[i]; }
    tsum[tid] = cnt;
    __syncthreads();
    if (tid == 0) {
        int acc = 0;
        for (int i = 0; i < 256; i++) { int c = tsum[i]; tsum[i] = acc; acc += c; }
        total_sh = acc;
        g_valid[b] = acc;
    }
    __syncthreads();
    int off = tsum[tid];
#pragma unroll
    for (int i = 0; i < 8; i++) {
        g_cidx[b * SEQ + base + i] = v[i] ? off : -1;
        off += v[i];
    }
    const int total = total_sh;
    for (int j = tid; j < SEQ; j += 256)
        g_addm[b * SEQ + j] = (j < total) ? -SOFTC : -1.0e30f;
}

// zero k/v pad rows [valid, ceil128(valid)) per (b,h) — keeps tail tiles finite
__global__ __launch_bounds__(128) void padzero_kernel(void)
{
    const int bh = blockIdx.x;
    const int b = bh / NHEAD;
    const int valid = g_valid[b];
    const int padend = (valid + 127) & ~127;
    const int nrows = padend - valid;
    const size_t base = (size_t)bh * SEQ * HDIM;
    for (int idx = threadIdx.x; idx < nrows * (HDIM / 2); idx += 128) {
        int row = valid + idx / (HDIM / 2);
        int c = (idx % (HDIM / 2)) * 2;
        *(uint32_t*)(g_kf + base + (size_t)row * HDIM + c) = 0;
        *(uint32_t*)(g_vf + base + (size_t)row * HDIM + c) = 0;
    }
}

// =====================================================================
// Fused prep: X fp32->fp16, 4 weights fp32->fp16.
// =====================================================================
#define NX4 (MROWS*HID/4)       // 1572864
#define NW4 (HID*HID/4)         // 147456
#define XBLK (NX4/256)          // 6144
#define WBLK (NW4/256)          // 576

__global__ __launch_bounds__(256) void prep_kernel(
    const float* __restrict__ X,
    const float* __restrict__ W0, const float* __restrict__ W1,
    const float* __restrict__ W2, const float* __restrict__ W3)
{
    const int bid = blockIdx.x;
    if (bid < XBLK) {
        int i = bid * 256 + threadIdx.x;
        float4 v = *(const float4*)(X + (size_t)i * 4);
        *(uint2*)(g_xf + (size_t)i * 4) =
            make_uint2(cvt_h2(v.y, v.x), cvt_h2(v.w, v.z));
    } else {
        int wb = bid - XBLK;
        int which = wb / WBLK;
        int i = (wb - which * WBLK) * 256 + threadIdx.x;
        const float* src = (which == 0) ? W0 : (which == 1) ? W1
                         : (which == 2) ? W2 : W3;
        __half* dst = g_wf + (size_t)which * HID * HID;
        float4 v = *(const float4*)(src + (size_t)i * 4);
        *(uint2*)(dst + (size_t)i * 4) =
            make_uint2(cvt_h2(v.y, v.x), cvt_h2(v.w, v.z));
    }
}
#define PREP_BLOCKS (XBLK + 4*WBLK)

// =====================================================================
// HMMA GEMM fp16 (R11 champion): BK=64 double-buffered, pitch 72.
// QKV (is_oproj=0): q -> [b,h,s,d]; k/v -> COMPACTED via g_cidx scatter.
// O-proj: +bias+residual fp32 -> g_y.
// =====================================================================
#define GP4   72
#define REG4  (128*GP4)
#define BUF4  (2*REG4)
#define GEMM_SMEM_BYTES (2*BUF4*2)   // 73728 B

__global__ __launch_bounds__(256, 2) void hmma_gemm(
    const __half* __restrict__ A,
    const float* __restrict__ b0, const float* __restrict__ b1,
    const float* __restrict__ b2, const float* __restrict__ residual,
    int is_oproj)
{
    extern __shared__ char smraw[];
    const uint32_t sbu = smem_u32(smraw);
    const int tid = threadIdx.x;
    const int lane = tid & 31;
    const int wid = tid >> 5;
    const int wm = wid >> 2;
    const int wn = wid & 3;

    const int n0 = blockIdx.x * 128;
    const int m0 = blockIdx.y * 128;
    const int z  = blockIdx.z;
    const int which = is_oproj ? 3 : z;

    const __half* Bg = g_wf + (size_t)which * HID * HID;
    const float* bias = is_oproj ? b0 : (z == 0 ? b0 : (z == 1 ? b1 : b2));

    float acc[4][4][4];
#pragma unroll
    for (int i = 0; i < 4; i++)
#pragma unroll
        for (int j = 0; j < 4; j++)
#pragma unroll
            for (int r = 0; r < 4; r++) acc[i][j][r] = 0.f;

    auto issue = [&](int c, int buf) {
        const int k0 = c * 64;
        const uint32_t base = sbu + (uint32_t)(buf * BUF4) * 2;
#pragma unroll
        for (int it = 0; it < 4; it++) {
            int idx = tid + it * 256;
            int row = idx >> 3;
            int ch  = idx & 7;
            uint32_t so = (uint32_t)(row * GP4 + swz(row, ch) * 8) * 2;
            cp16(base +          so, A  + (size_t)(m0 + row) * HID + k0 + ch * 8);
            cp16(base + REG4*2 + so, Bg + (size_t)(n0 + row) * HID + k0 + ch * 8);
        }
    };

    issue(0, 0); CP_COMMIT();

    const int NC = HID / 64;   // 12
    for (int c = 0; c < NC; c++) {
        if (c + 1 < NC) { issue(c + 1, (c + 1) & 1); CP_COMMIT(); cp_wait<1>(); }
        else            cp_wait<0>();
        __syncthreads();

        const uint32_t S = sbu + (uint32_t)((c & 1) * BUF4) * 2;

#pragma unroll
        for (int ks = 0; ks < 4; ks++) {
            uint32_t b[2][4];
#pragma unroll
            for (int p = 0; p < 2; p++) {
                int row = wn * 32 + p * 16 + ((lane >> 4) & 1) * 8 + (lane & 7);
                int ch  = ks * 2 + ((lane >> 3) & 1);
                ldsm_x4(b[p], S + REG4 * 2
                              + (uint32_t)(row * GP4 + swz(row, ch) * 8) * 2);
            }
#pragma unroll
            for (int mt = 0; mt < 4; mt++) {
                int row = wm * 64 + mt * 16 + (lane & 15);
                int ch  = ks * 2 + (lane >> 4);
                uint32_t a[4];
                ldsm_x4(a, S + (uint32_t)(row * GP4 + swz(row, ch) * 8) * 2);
#pragma unroll
                for (int p = 0; p < 2; p++) {
                    mma_f16(acc[mt][2*p],   a, b[p]);
                    mma_f16(acc[mt][2*p+1], a, b[p] + 2);
                }
            }
        }
        __syncthreads();
    }

    // ---------------- epilogue ----------------
    const int fr = lane >> 2;
    const int j2 = (lane & 3) * 2;
    if (!is_oproj) {
        const float scale = (z == 0) ? (0.125f * LOG2E) : 1.0f;
        __half* of = (z == 0) ? g_qf : (z == 1 ? g_kf : g_vf);
        int ci[4][2];
        if (z != 0) {
#pragma unroll
            for (int mt = 0; mt < 4; mt++)
#pragma unroll
                for (int half = 0; half < 2; half++) {
                    int m = m0 + wm * 64 + mt * 16 + fr + half * 8;
                    ci[mt][half] = g_cidx[(m >> 11) * SEQ + (m & 2047)];
                }
        }
#pragma unroll
        for (int nt = 0; nt < 4; nt++) {
            const int n = n0 + wn * 32 + nt * 8 + j2;
            const float bv0 = bias[n], bv1 = bias[n + 1];
            const int h = n >> 6, d = n & 63;
#pragma unroll
            for (int mt = 0; mt < 4; mt++) {
#pragma unroll
                for (int half = 0; half < 2; half++) {
                    const int m = m0 + wm * 64 + mt * 16 + fr + half * 8;
                    float s0 = (acc[mt][nt][half * 2 + 0] + bv0) * scale;
                    float s1 = (acc[mt][nt][half * 2 + 1] + bv1) * scale;
                    const int bI = m >> 11;
                    int sI;
                    if (z == 0) {
                        sI = m & 2047;
                    } else {
                        sI = ci[mt][half];
                        if (sI < 0) continue;
                    }
                    size_t off = ((size_t)(bI * NHEAD + h) * SEQ + sI) * HDIM + d;
                    *(uint32_t*)(of + off) = cvt_h2(s1, s0);
                }
            }
        }
    } else {
#pragma unroll
        for (int nt = 0; nt < 4; nt++) {
            const int n = n0 + wn * 32 + nt * 8 + j2;
            const float bv0 = bias[n], bv1 = bias[n + 1];
#pragma unroll
            for (int mt = 0; mt < 4; mt++) {
#pragma unroll
                for (int half = 0; half < 2; half++) {
                    const int m = m0 + wm * 64 + mt * 16 + fr + half * 8;
                    float v0 = acc[mt][nt][half * 2 + 0];
                    float v1 = acc[mt][nt][half * 2 + 1];
                    size_t off = (size_t)m * HID + n;
                    float2 res = *(const float2*)(residual + off);
                    float2 r = make_float2(v0 + bv0 + res.x, v1 + bv1 + res.y);
                    *(float2*)(g_y + off) = r;
                }
            }
        }
    }
}

// =====================================================================
// Flash attention (R11 champion + compacted KV): dynamic tile count
// NT = ceil(valid[b]/128). Everything else identical.
// =====================================================================
#define AQP 72
#define A_QE    (128*AQP)
#define A_OPE   (128*AQP)
#define A_BUFE  (2*A_OPE)
#define ATTN_SMEM ((A_QE + 2*A_BUFE)*2)   // 92160 B

__global__ __launch_bounds__(256, 2) void attn_hmma(void)
{
    extern __shared__ char smraw[];
    const uint32_t sbu = smem_u32(smraw);

    const int q0 = blockIdx.x * 128;
    const int bh = blockIdx.y;
    const int b  = bh / NHEAD, h = bh % NHEAD;
    const int tid = threadIdx.x;
    const int lane = tid & 31;
    const int w = tid >> 5;

    const float* addm = g_addm + b * SEQ;
    const int NT = (g_valid[b] + 127) >> 7;   // compact KV tiles

    const size_t bh_off = (size_t)bh * SEQ * HDIM;
    const __half* qf = g_qf + bh_off + (size_t)q0 * HDIM;

    // Q tile load (group A)
#pragma unroll
    for (int it = 0; it < 4; it++) {
        int idx = tid + it * 256;
        int row = idx >> 3, ch = idx & 7;
        uint32_t so = (uint32_t)(row * AQP + swz(row, ch) * 8) * 2;
        cp16(sbu + so, qf + row * HDIM + ch * 8);
    }
    CP_COMMIT();

    auto issue_kv = [&](int t, int buf) {
        const int kv0 = t * 128;
        uint32_t base = sbu + (uint32_t)(A_QE + buf * A_BUFE) * 2;
        const __half* kf = g_kf + bh_off + (size_t)kv0 * HDIM;
        const __half* vf = g_vf + bh_off + (size_t)kv0 * HDIM;
#pragma unroll
        for (int it = 0; it < 4; it++) {
            int idx = tid + it * 256;
            int row = idx >> 3, ch = idx & 7;
            uint32_t so = (uint32_t)(row * AQP + swz(row, ch) * 8) * 2;
            int go = row * HDIM + ch * 8;
            cp16(base +             so, kf + go);
            cp16(base + A_OPE * 2 + so, vf + go);
        }
    };

    issue_kv(0, 0);
    CP_COMMIT();

    // wait for Q, hoist Q fragments
    cp_wait<1>();
    __syncthreads();
    uint32_t qfr[4][4];
#pragma unroll
    for (int kt = 0; kt < 4; kt++) {
        int qrow = w * 16 + (lane & 15);
        int qch  = kt * 2 + (lane >> 4);
        ldsm_x4(qfr[kt], sbu + (uint32_t)(qrow * AQP + swz(qrow, qch) * 8) * 2);
    }

    float S[8][4], O[8][4];
    float l0 = 0.f, l1 = 0.f;
#pragma unroll
    for (int j = 0; j < 8; j++)
#pragma unroll
        for (int r = 0; r < 4; r++) O[j][r] = 0.f;

    const int ln8 = lane & 7;
    const int sel = lane >> 3;
    const int c2  = (lane & 3) * 2;
    const int fr  = lane >> 2;

    for (int t = 0; t < NT; t++) {
        if (t + 1 < NT) { issue_kv(t + 1, (t + 1) & 1); CP_COMMIT(); cp_wait<1>(); }
        else            cp_wait<0>();
        __syncthreads();

        const uint32_t kb = sbu + (uint32_t)(A_QE + (t & 1) * A_BUFE) * 2;

#pragma unroll
        for (int sub = 0; sub < 2; sub++) {
            const int r64 = sub * 64;

#pragma unroll
            for (int j = 0; j < 8; j++)
#pragma unroll
                for (int r = 0; r < 4; r++) S[j][r] = 0.f;

            // ---- QK^T (Q frags from registers) ----
#pragma unroll
            for (int kt = 0; kt < 4; kt++) {
#pragma unroll
                for (int jp = 0; jp < 4; jp++) {
                    int krow = r64 + jp * 16 + (sel >> 1) * 8 + ln8;
                    int kch  = kt * 2 + (sel & 1);
                    uint32_t boff = (uint32_t)(krow * AQP + swz(krow, kch) * 8) * 2;
                    uint32_t bf[4];
                    ldsm_x4(bf, kb + boff);
                    mma_f16(S[2*jp],   qfr[kt], bf);
                    mma_f16(S[2*jp+1], qfr[kt], bf + 2);
                }
            }

            // ---- fixed-offset softmax: p = ex2(s' + addm) ----
            const int kv0 = t * 128 + r64;
#pragma unroll
            for (int j = 0; j < 8; j++) {
                float2 av = *(const float2*)&addm[kv0 + j * 8 + c2];
                S[j][0] = ex2f(S[j][0] + av.x);
                S[j][1] = ex2f(S[j][1] + av.y);
                S[j][2] = ex2f(S[j][2] + av.x);
                S[j][3] = ex2f(S[j][3] + av.y);
                l0 += S[j][0] + S[j][1];
                l1 += S[j][2] + S[j][3];
            }

            // ---- P pack fp16 and PV ----
#pragma unroll
            for (int kt2 = 0; kt2 < 4; kt2++) {
                uint32_t pa[4];
#pragma unroll
                for (int half = 0; half < 2; half++) {
                    const int jt = 2 * kt2 + half;
                    pa[half * 2 + 0] = cvt_h2(S[jt][1], S[jt][0]);
                    pa[half * 2 + 1] = cvt_h2(S[jt][3], S[jt][2]);
                }
#pragma unroll
                for (int jp = 0; jp < 4; jp++) {
                    int vrow = r64 + kt2 * 16 + (sel & 1) * 8 + ln8;
                    int vch  = jp * 2 + (sel >> 1);
                    uint32_t voff = (uint32_t)(vrow * AQP + swz(vrow, vch) * 8) * 2;
                    uint32_t vf[4];
                    ldsm_x4t(vf, kb + A_OPE * 2 + voff);
                    mma_f16(O[2*jp],   pa, vf);
                    mma_f16(O[2*jp+1], pa, vf + 2);
                }
            }
        }
        __syncthreads();
    }

    // ---- epilogue: one cross-lane reduction, normalize, store fp16 ctx ----
    l0 += __shfl_xor_sync(0xffffffffu, l0, 1);
    l0 += __shfl_xor_sync(0xffffffffu, l0, 2);
    l1 += __shfl_xor_sync(0xffffffffu, l1, 1);
    l1 += __shfl_xor_sync(0xffffffffu, l1, 2);
    const float i0 = 1.0f / l0, i1 = 1.0f / l1;
    const int q = q0 + w * 16 + fr;
#pragma unroll
    for (int j = 0; j < 8; j++) {
        const int d = h * HDIM + j * 8 + c2;
        size_t r0 = (size_t)(b * SEQ + q) * HID + d;
        size_t r1 = (size_t)(b * SEQ + q + 8) * HID + d;
        *(uint32_t*)(g_cf + r0) = cvt_h2(O[j][1] * i0, O[j][0] * i0);
        *(uint32_t*)(g_cf + r1) = cvt_h2(O[j][3] * i1, O[j][2] * i1);
    }
}

// =====================================================================
// LayerNorm over last dim (768): 192 threads x float4 per row
// =====================================================================
__global__ __launch_bounds__(192) void ln_kernel(
    const float* __restrict__ gamma, const float* __restrict__ beta,
    float* __restrict__ out)
{
    const int r = blockIdx.x;
    const float* row = g_y + (size_t)r * HID;
    const int tid = threadIdx.x;

    float4 v = *(const float4*)(row + tid * 4);
    float s  = v.x + v.y + v.z + v.w;
    float s2 = v.x*v.x + v.y*v.y + v.z*v.z + v.w*v.w;
#pragma unroll
    for (int off = 16; off; off >>= 1) {
        s  += __shfl_xor_sync(0xffffffffu, s,  off);
        s2 += __shfl_xor_sync(0xffffffffu, s2, off);
    }
    __shared__ float sm_s[6], sm_s2[6];
    int w = tid >> 5, lane = tid & 31;
    if (lane == 0) { sm_s[w] = s; sm_s2[w] = s2; }
    __syncthreads();
    if (tid == 0) {
        float a = 0.f, b2 = 0.f;
#pragma unroll
        for (int i = 0; i < 6; i++) { a += sm_s[i]; b2 += sm_s2[i]; }
        sm_s[0] = a; sm_s2[0] = b2;
    }
    __syncthreads();
    s = sm_s[0]; s2 = sm_s2[0];

    float mean = s * (1.0f / HID);
    float var  = s2 * (1.0f / HID) - mean * mean;
    float rstd = rsqrtf(var + 1e-5f);

    float4 g = *(const float4*)(gamma + tid * 4);
    float4 bb = *(const float4*)(beta + tid * 4);
    float4 o;
    o.x = (v.x - mean) * rstd * g.x + bb.x;
    o.y = (v.y - mean) * rstd * g.y + bb.y;
    o.z = (v.z - mean) * rstd * g.z + bb.z;
    o.w = (v.w - mean) * rstd * g.w + bb.w;
    *(float4*)(out + (size_t)r * HID + tid * 4) = o;
}

// =====================================================================
extern "C" void kernel_launch(void* const* d_in, const int* in_sizes, int n_in,
                              void* d_out, int out_size)
{
    const float* hidden     = (const float*)d_in[0];
    const float* Wq         = (const float*)d_in[1];
    const float* bq         = (const float*)d_in[2];
    const float* Wk         = (const float*)d_in[3];
    const float* bk         = (const float*)d_in[4];
    const float* Wv         = (const float*)d_in[5];
    const float* bv         = (const float*)d_in[6];
    const float* Wo         = (const float*)d_in[7];
    const float* bo         = (const float*)d_in[8];
    const float* ln_gamma   = (const float*)d_in[10];
    const float* ln_beta    = (const float*)d_in[11];
    const int*   attn_mask  = (const int*)d_in[12];
    float* out = (float*)d_out;

    cudaFuncSetAttribute(hmma_gemm, cudaFuncAttributeMaxDynamicSharedMemorySize,
                         GEMM_SMEM_BYTES);
    cudaFuncSetAttribute(attn_hmma, cudaFuncAttributeMaxDynamicSharedMemorySize,
                         ATTN_SMEM);

    __half *xf, *cf;
    cudaGetSymbolAddress((void**)&xf, g_xf);
    cudaGetSymbolAddress((void**)&cf, g_cf);

    // mask scan -> compact index map, valid counts, additive table
    scan_kernel<<<BATCH, 256>>>(attn_mask);

    // converts
    prep_kernel<<<PREP_BLOCKS, 256>>>(hidden, Wq, Wk, Wv, Wo);

    // zero k/v pad rows (before attention; disjoint from QKV writes)
    padzero_kernel<<<BATCH * NHEAD, 128>>>();

    // QKV projections -> q [b,h,s,d]; k/v compacted via cidx scatter
    hmma_gemm<<<dim3(HID/128, MROWS/128, 3), 256, GEMM_SMEM_BYTES>>>(
        xf, bq, bk, bv, nullptr, 0);

    // attention over compacted KV (fixed-offset softmax) -> ctx fp16
    attn_hmma<<<dim3(SEQ/128, BATCH*NHEAD), 256, ATTN_SMEM>>>();

    // O projection (+bias +residual) -> g_y
    hmma_gemm<<<dim3(HID/128, MROWS/128, 1), 256, GEMM_SMEM_BYTES>>>(
        cf, bo, nullptr, nullptr, hidden, 1);

    // layernorm
    ln_kernel<<<MROWS, 192>>>(ln_gamma, ln_beta, out);
}